// round 1
// baseline (speedup 1.0000x reference)
#include <cuda_runtime.h>
#include <cuda_bf16.h>
#include <math.h>

#define L 4096
#define DM 1024
#define DIN 2048
#define NH 32
#define HD 64
#define NST 128
#define CONVD 2560
#define DPROJ 4672
#define CHK 128
#define NC 32
#define EPSV 1e-5f

// ---------------- scratch (static device globals; no allocation) ----------------
__device__ float g_zx[(size_t)L * DPROJ];        // in_proj output (4096 x 4672)
__device__ float g_xc[(size_t)L * CONVD];        // conv+silu output (x_og | BC)
__device__ float g_dt2[2 * L * NH];              // softplus dt, both dirs
__device__ float g_Bm[(size_t)2 * L * NST];      // B per dir (flipped for dir1)
__device__ float g_Cm[(size_t)2 * L * NST];      // C per dir
__device__ float g_xdt[(size_t)2 * L * DIN];     // x (flipped) * dt
__device__ float g_Acs[2 * NC * NH * CHK];       // per-chunk cumsum of A*dt
__device__ float g_G[(size_t)2 * NC * CHK * CHK];// C B^T per (dir,chunk)
__device__ float g_Yd[(size_t)2 * L * DIN];      // Y (diag then += off + x*D)
__device__ float g_states[(size_t)2 * NC * NH * HD * NST];
__device__ float g_fd[L * NH];
__device__ float g_yn[(size_t)L * DIN];          // normalized gated output

__device__ __forceinline__ float sigmoidf_(float x) { return 1.f / (1.f + expf(-x)); }

// ---------------- generic NT SGEMM: C[m,n] = sum_k A[m*K+k] * B[n*K+k], batched in z --------
__global__ __launch_bounds__(256) void sgemm_nt(const float* __restrict__ A,
                                                const float* __restrict__ B,
                                                float* __restrict__ C,
                                                int M, int N, int K,
                                                long sA, long sB, long sC) {
    A += (size_t)blockIdx.z * sA;
    B += (size_t)blockIdx.z * sB;
    C += (size_t)blockIdx.z * sC;
    __shared__ float As[16][128];
    __shared__ float Bs[16][128];
    int tid = threadIdx.x;
    int bRow = blockIdx.y * 128, bCol = blockIdx.x * 128;
    int tx = tid & 15, ty = tid >> 4;
    float acc[8][8] = {};
    int lr = tid >> 2;            // 0..63
    int lk = (tid & 3) * 4;       // 0,4,8,12
    for (int kt = 0; kt < K; kt += 16) {
#pragma unroll
        for (int p = 0; p < 2; p++) {
            int r = lr + p * 64;
            int row = bRow + r;
            float4 v = make_float4(0.f, 0.f, 0.f, 0.f);
            if (row < M) v = *(const float4*)(A + (size_t)row * K + kt + lk);
            As[lk][r] = v.x; As[lk + 1][r] = v.y; As[lk + 2][r] = v.z; As[lk + 3][r] = v.w;
            int col = bCol + r;
            float4 w = make_float4(0.f, 0.f, 0.f, 0.f);
            if (col < N) w = *(const float4*)(B + (size_t)col * K + kt + lk);
            Bs[lk][r] = w.x; Bs[lk + 1][r] = w.y; Bs[lk + 2][r] = w.z; Bs[lk + 3][r] = w.w;
        }
        __syncthreads();
#pragma unroll
        for (int k = 0; k < 16; k++) {
            float ra[8], rb[8];
            *(float4*)ra       = *(const float4*)&As[k][ty * 8];
            *(float4*)(ra + 4) = *(const float4*)&As[k][ty * 8 + 4];
            *(float4*)rb       = *(const float4*)&Bs[k][tx * 8];
            *(float4*)(rb + 4) = *(const float4*)&Bs[k][tx * 8 + 4];
#pragma unroll
            for (int i = 0; i < 8; i++)
#pragma unroll
                for (int j = 0; j < 8; j++)
                    acc[i][j] += ra[i] * rb[j];
        }
        __syncthreads();
    }
    for (int i = 0; i < 8; i++) {
        int row = bRow + ty * 8 + i;
        if (row >= M) continue;
        for (int j = 0; j < 8; j++) {
            int col = bCol + tx * 8 + j;
            if (col < N) C[(size_t)row * N + col] = acc[i][j];
        }
    }
}

// ---------------- depthwise causal conv (k=4) + bias + silu ----------------
__global__ void conv_kernel(const float* __restrict__ cw, const float* __restrict__ cb) {
    size_t idx = (size_t)blockIdx.x * blockDim.x + threadIdx.x;
    if (idx >= (size_t)L * CONVD) return;
    int c = (int)(idx % CONVD);
    int t = (int)(idx / CONVD);
    float acc = cb[c];
#pragma unroll
    for (int k = 0; k < 4; k++) {
        int ts = t - 3 + k;
        if (ts >= 0) acc += cw[c * 4 + k] * g_zx[(size_t)ts * DPROJ + DIN + c];
    }
    g_xc[idx] = acc * sigmoidf_(acc);
}

// ---------------- dt (with direction flip) + softplus ----------------
__global__ void dt_kernel(const float* __restrict__ dt_bias) {
    int idx = blockIdx.x * blockDim.x + threadIdx.x;
    if (idx >= 2 * L * NH) return;
    int h = idx & 31;
    int t = (idx >> 5) & (L - 1);
    int dir = idx >> 17;
    int ts = dir ? (L - 1 - t) : t;
    float v = g_zx[(size_t)ts * DPROJ + DIN + CONVD + dir * NH + h] + dt_bias[h];
    g_dt2[idx] = (v > 20.f) ? v : log1pf(expf(v));
}

// ---------------- B/C split per direction (flip for dir1) ----------------
__global__ void prep_bc_kernel() {
    int idx = blockIdx.x * blockDim.x + threadIdx.x;
    if (idx >= 2 * L * NST) return;
    int n = idx & 127;
    int t = (idx >> 7) & (L - 1);
    int dir = idx >> 19;
    int ts = dir ? (L - 1 - t) : t;
    int off = dir ? 256 : 0;
    const float* p = g_xc + (size_t)ts * CONVD + DIN + off;
    g_Bm[idx] = p[n];
    g_Cm[idx] = p[NST + n];
}

// ---------------- x (flipped) * dt ----------------
__global__ void prep_x_kernel() {
    size_t idx = (size_t)blockIdx.x * blockDim.x + threadIdx.x;
    if (idx >= (size_t)2 * L * DIN) return;
    int d = (int)(idx & 2047);
    int t = (int)((idx >> 11) & (L - 1));
    int dir = (int)(idx >> 23);
    int ts = dir ? (L - 1 - t) : t;
    g_xdt[idx] = g_xc[(size_t)ts * CONVD + d] * g_dt2[((dir << 12) | t) * NH + (d >> 6)];
}

// ---------------- per-chunk cumsum of A*dt ----------------
__global__ void acs_kernel(const float* __restrict__ A_log) {
    int c = blockIdx.x, dir = blockIdx.y, h = threadIdx.x;
    float Ah = -expf(A_log[h]);
    float cum = 0.f;
    float* out = g_Acs + (((dir * NC + c) * NH + h) << 7);
    const float* dtp = g_dt2 + ((size_t)(dir * L + c * CHK)) * NH + h;
    for (int l = 0; l < CHK; l++) {
        cum += Ah * dtp[l * NH];
        out[l] = cum;
    }
}

// ---------------- per (dir,chunk,head): Y_diag = (G.*Lmat)@xdt ; states = B^T @ (decay.*xdt) ----
__global__ __launch_bounds__(256) void ydiag_states_kernel() {
    int b = blockIdx.x;
    int h = b & 31, c = (b >> 5) & 31, dir = b >> 10;
    int tid = threadIdx.x;
    __shared__ float sAcs[CHK];
    __shared__ float sMl[CHK][17];
    __shared__ float sXs[16][68];
    __shared__ float sB[16][132];
    __shared__ float sXd[16][68];
    if (tid < CHK) sAcs[tid] = g_Acs[(b << 7) + tid];
    __syncthreads();
    const float* Gp = g_G + ((size_t)(dir * NC + c) << 14);
    const float* Xp = g_xdt + ((size_t)(dir * L + c * CHK)) * DIN + h * HD;
    int tx = tid & 15, ty = tid >> 4;
    float acc[8][4] = {};
    int l0 = tid >> 1, skb = (tid & 1) * 8;
    for (int st = 0; st < 8; st++) {
#pragma unroll
        for (int i = 0; i < 8; i++) {
            int s = st * 16 + skb + i;
            float g = Gp[l0 * CHK + s];
            sMl[l0][skb + i] = (l0 >= s) ? g * expf(sAcs[l0] - sAcs[s]) : 0.f;
        }
        {
            int sk = tid >> 4, p0 = (tid & 15) * 4;
            float4 v = *(const float4*)(Xp + (size_t)(st * 16 + sk) * DIN + p0);
            sXs[sk][p0] = v.x; sXs[sk][p0 + 1] = v.y; sXs[sk][p0 + 2] = v.z; sXs[sk][p0 + 3] = v.w;
        }
        __syncthreads();
#pragma unroll
        for (int sk = 0; sk < 16; sk++) {
            float xb0 = sXs[sk][tx * 4], xb1 = sXs[sk][tx * 4 + 1];
            float xb2 = sXs[sk][tx * 4 + 2], xb3 = sXs[sk][tx * 4 + 3];
#pragma unroll
            for (int i = 0; i < 8; i++) {
                float m = sMl[ty * 8 + i][sk];
                acc[i][0] += m * xb0; acc[i][1] += m * xb1;
                acc[i][2] += m * xb2; acc[i][3] += m * xb3;
            }
        }
        __syncthreads();
    }
    float* Yp = g_Yd + ((size_t)(dir * L + c * CHK)) * DIN + h * HD;
#pragma unroll
    for (int i = 0; i < 8; i++)
#pragma unroll
        for (int j = 0; j < 4; j++)
            Yp[(size_t)(ty * 8 + i) * DIN + tx * 4 + j] = acc[i][j];

    // ---- states ----
    float accS[8][4] = {};
    int n0 = (tid & 31) * 4;
    int p0s = (tid >> 5) * 8;
    float lastA = sAcs[127];
    const float* Bp = g_Bm + ((size_t)(dir * L + c * CHK)) * NST;
    for (int lt = 0; lt < 8; lt++) {
        {
            int lk = tid >> 4, nb = (tid & 15) * 8;
            float4 v0 = *(const float4*)(Bp + (size_t)(lt * 16 + lk) * NST + nb);
            float4 v1 = *(const float4*)(Bp + (size_t)(lt * 16 + lk) * NST + nb + 4);
            sB[lk][nb] = v0.x; sB[lk + 1 - 1][nb + 1] = v0.y; sB[lk][nb + 2] = v0.z; sB[lk][nb + 3] = v0.w;
            sB[lk][nb + 4] = v1.x; sB[lk][nb + 5] = v1.y; sB[lk][nb + 6] = v1.z; sB[lk][nb + 7] = v1.w;
            int pb = (tid & 15) * 4;
            float dec = expf(lastA - sAcs[lt * 16 + lk]);
            float4 xv = *(const float4*)(Xp + (size_t)(lt * 16 + lk) * DIN + pb);
            sXd[lk][pb] = xv.x * dec; sXd[lk][pb + 1] = xv.y * dec;
            sXd[lk][pb + 2] = xv.z * dec; sXd[lk][pb + 3] = xv.w * dec;
        }
        __syncthreads();
#pragma unroll
        for (int lk2 = 0; lk2 < 16; lk2++) {
            float pv[8];
#pragma unroll
            for (int i = 0; i < 8; i++) pv[i] = sXd[lk2][p0s + i];
            float nv0 = sB[lk2][n0], nv1 = sB[lk2][n0 + 1];
            float nv2 = sB[lk2][n0 + 2], nv3 = sB[lk2][n0 + 3];
#pragma unroll
            for (int i = 0; i < 8; i++) {
                accS[i][0] += pv[i] * nv0; accS[i][1] += pv[i] * nv1;
                accS[i][2] += pv[i] * nv2; accS[i][3] += pv[i] * nv3;
            }
        }
        __syncthreads();
    }
    float* Sp = g_states + ((size_t)b << 13);
#pragma unroll
    for (int i = 0; i < 8; i++)
#pragma unroll
        for (int j = 0; j < 4; j++)
            Sp[(size_t)(p0s + i) * NST + n0 + j] = accS[i][j];
}

// ---------------- inter-chunk recurrence (in place: states[c] becomes state USED by chunk c) ----
__global__ void recur_kernel() {
    int b = blockIdx.x;           // dir*NH + h
    int dir = b >> 5, h = b & 31;
    int tid = threadIdx.x;
    float Hreg[32];
#pragma unroll
    for (int k = 0; k < 32; k++) Hreg[k] = 0.f;
    for (int c = 0; c < NC; c++) {
        int sb = (dir * NC + c) * NH + h;
        float dec = expf(g_Acs[(sb << 7) + 127]);
        size_t base = ((size_t)sb << 13);
#pragma unroll
        for (int k = 0; k < 32; k++) {
            size_t off = base + tid + k * 256;
            float s = g_states[off];
            g_states[off] = Hreg[k];
            Hreg[k] = dec * Hreg[k] + s;
        }
    }
}

// ---------------- Y_off = exp(Acs[l]) * C @ state^T ; Yd += Y_off + x*D ----------------
__global__ __launch_bounds__(256) void yoff_kernel(const float* __restrict__ Dv) {
    int b = blockIdx.x;
    int h = b & 31, c = (b >> 5) & 31, dir = b >> 10;
    int tid = threadIdx.x;
    __shared__ float sAcs[CHK];
    __shared__ float sC[CHK][17];
    __shared__ float sS[64][17];
    if (tid < CHK) sAcs[tid] = g_Acs[(b << 7) + tid];
    __syncthreads();
    const float* Cp = g_Cm + ((size_t)(dir * L + c * CHK)) * NST;
    const float* Sp = g_states + ((size_t)b << 13);
    int tx = tid & 15, ty = tid >> 4;
    float acc[8][4] = {};
    int l0 = tid >> 1, nkb = (tid & 1) * 8;
    int p1 = tid >> 2, nkb2 = (tid & 3) * 4;
    for (int nt = 0; nt < 8; nt++) {
#pragma unroll
        for (int i = 0; i < 8; i++)
            sC[l0][nkb + i] = Cp[(size_t)l0 * NST + nt * 16 + nkb + i];
        {
            float4 v = *(const float4*)(Sp + (size_t)p1 * NST + nt * 16 + nkb2);
            sS[p1][nkb2] = v.x; sS[p1][nkb2 + 1] = v.y;
            sS[p1][nkb2 + 2] = v.z; sS[p1][nkb2 + 3] = v.w;
        }
        __syncthreads();
#pragma unroll
        for (int nk = 0; nk < 16; nk++) {
            float sv0 = sS[tx * 4][nk], sv1 = sS[tx * 4 + 1][nk];
            float sv2 = sS[tx * 4 + 2][nk], sv3 = sS[tx * 4 + 3][nk];
#pragma unroll
            for (int i = 0; i < 8; i++) {
                float cv = sC[ty * 8 + i][nk];
                acc[i][0] += cv * sv0; acc[i][1] += cv * sv1;
                acc[i][2] += cv * sv2; acc[i][3] += cv * sv3;
            }
        }
        __syncthreads();
    }
    float Dh = Dv[h];
    float* Yp = g_Yd + ((size_t)(dir * L + c * CHK)) * DIN + h * HD;
#pragma unroll
    for (int i = 0; i < 8; i++) {
        int l = ty * 8 + i;
        float e = expf(sAcs[l]);
        int tglob = c * CHK + l;
        int ts = dir ? (L - 1 - tglob) : tglob;
        const float* xrow = g_xc + (size_t)ts * CONVD + h * HD;
#pragma unroll
        for (int j = 0; j < 4; j++) {
            int p = tx * 4 + j;
            size_t o = (size_t)l * DIN + p;
            Yp[o] = Yp[o] + e * acc[i][j] + xrow[p] * Dh;
        }
    }
}

// ---------------- fd[t,h] = x_og[t] . fc_D_w[h] + D[h] ----------------
__global__ void fcD_kernel(const float* __restrict__ W, const float* __restrict__ Dv) {
    int t = blockIdx.x;
    __shared__ float sx[DIN];
    int tid = threadIdx.x;
#pragma unroll
    for (int k = 0; k < 8; k++) sx[tid + k * 256] = g_xc[(size_t)t * CONVD + tid + k * 256];
    __syncthreads();
    int warp = tid >> 5, lane = tid & 31;
    for (int q = 0; q < 4; q++) {
        int h = warp * 4 + q;
        const float* wr = W + (size_t)h * DIN;
        float acc = 0.f;
        for (int i = 0; i < 64; i++) {
            int d = i * 32 + lane;
            acc += sx[d] * wr[d];
        }
        for (int o = 16; o > 0; o >>= 1) acc += __shfl_down_sync(0xffffffffu, acc, o);
        if (lane == 0) g_fd[t * NH + h] = acc + Dv[h];
    }
}

// ---------------- shift + merge dirs + skip + gate + RMSNorm ----------------
__global__ void combine_kernel(const float* __restrict__ norm_w) {
    int t = blockIdx.x;
    int tid = threadIdx.x;
    __shared__ float red[256];
    __shared__ float sc;
    float yg[8];
    float ss = 0.f;
#pragma unroll
    for (int k = 0; k < 8; k++) {
        int d = tid + k * 256;
        float yfw = (t > 0) ? g_Yd[((size_t)(t - 1)) * DIN + d] : 0.f;
        float ybw = (t < L - 1) ? g_Yd[((size_t)(L + (L - 2 - t))) * DIN + d] : 0.f;
        float x = g_xc[(size_t)t * CONVD + d];
        float fdv = g_fd[t * NH + (d >> 6)];
        float z = g_zx[(size_t)t * DPROJ + d];
        float v = (yfw + ybw + x * fdv) * (z * sigmoidf_(z));
        yg[k] = v;
        ss += v * v;
    }
    red[tid] = ss;
    __syncthreads();
    for (int o = 128; o > 0; o >>= 1) {
        if (tid < o) red[tid] += red[tid + o];
        __syncthreads();
    }
    if (tid == 0) sc = rsqrtf(red[0] * (1.f / DIN) + EPSV);
    __syncthreads();
    float s = sc;
#pragma unroll
    for (int k = 0; k < 8; k++) {
        int d = tid + k * 256;
        g_yn[(size_t)t * DIN + d] = yg[k] * s * norm_w[d];
    }
}

extern "C" void kernel_launch(void* const* d_in, const int* in_sizes, int n_in,
                              void* d_out, int out_size) {
    const float* u          = (const float*)d_in[0];
    const float* in_proj_w  = (const float*)d_in[1];
    const float* conv_w     = (const float*)d_in[2];
    const float* conv_b     = (const float*)d_in[3];
    const float* dt_bias    = (const float*)d_in[4];
    const float* A_log      = (const float*)d_in[5];
    const float* Dv         = (const float*)d_in[6];
    const float* fc_D_w     = (const float*)d_in[7];
    const float* norm_w     = (const float*)d_in[8];
    const float* out_proj_w = (const float*)d_in[9];
    float* out = (float*)d_out;

    float *zx, *Bm, *Cm, *G, *yn;
    cudaGetSymbolAddress((void**)&zx, g_zx);
    cudaGetSymbolAddress((void**)&Bm, g_Bm);
    cudaGetSymbolAddress((void**)&Cm, g_Cm);
    cudaGetSymbolAddress((void**)&G, g_G);
    cudaGetSymbolAddress((void**)&yn, g_yn);

    // 1) in_proj: (4096 x 1024) @ (4672 x 1024)^T
    sgemm_nt<<<dim3((DPROJ + 127) / 128, (L + 127) / 128, 1), 256>>>(
        u, in_proj_w, zx, L, DPROJ, DM, 0, 0, 0);
    // 2) conv + silu
    conv_kernel<<<((size_t)L * CONVD + 255) / 256, 256>>>(conv_w, conv_b);
    // 3) dt softplus (both dirs)
    dt_kernel<<<(2 * L * NH + 255) / 256, 256>>>(dt_bias);
    // 4) B/C and x*dt prep
    prep_bc_kernel<<<(2 * L * NST + 255) / 256, 256>>>();
    prep_x_kernel<<<((size_t)2 * L * DIN + 255) / 256, 256>>>();
    // 5) per-chunk cumsum of A*dt
    acs_kernel<<<dim3(NC, 2), 32>>>(A_log);
    // 6) G = C B^T per (dir,chunk), batched
    sgemm_nt<<<dim3(1, 1, 2 * NC), 256>>>(Cm, Bm, G, CHK, CHK, NST,
                                          CHK * NST, CHK * NST, CHK * CHK);
    // 7) Y_diag + chunk states
    ydiag_states_kernel<<<2 * NC * NH, 256>>>();
    // 8) inter-chunk recurrence
    recur_kernel<<<2 * NH, 256>>>();
    // 9) Y_off + x*D
    yoff_kernel<<<2 * NC * NH, 256>>>(Dv);
    // 10) fd
    fcD_kernel<<<L, 256>>>(fc_D_w, Dv);
    // 11) shift/merge/gate/RMSNorm
    combine_kernel<<<L, 256>>>(norm_w);
    // 12) out_proj: (4096 x 2048) @ (1024 x 2048)^T
    sgemm_nt<<<dim3(DM / 128, L / 128, 1), 256>>>(yn, out_proj_w, out, L, DM, DIN, 0, 0, 0);
}

// round 3
// speedup vs baseline: 1.4344x; 1.4344x over previous
#include <cuda_runtime.h>
#include <cuda_bf16.h>
#include <math.h>
#include <stdint.h>

#define L 4096
#define DM 1024
#define DIN 2048
#define NH 32
#define HD 64
#define NST 128
#define CONVD 2560
#define DPROJ 4672
#define CHK 128
#define NC 32
#define EPSV 1e-5f

// ---------------- scratch (static device globals; no allocation) ----------------
__device__ float g_zx[(size_t)L * DPROJ];        // in_proj output (4096 x 4672)
__device__ float g_xc[(size_t)L * CONVD];        // conv+silu output (x_og | BC)
__device__ float g_dt2[2 * L * NH];              // softplus dt, both dirs
__device__ float g_Bm[(size_t)2 * L * NST];      // B per dir (flipped for dir1)
__device__ float g_Cm[(size_t)2 * L * NST];      // C per dir
__device__ float g_xdt[(size_t)2 * L * DIN];     // x (flipped) * dt
__device__ float g_Acs[2 * NC * NH * CHK];       // per-chunk cumsum of A*dt
__device__ float g_G[(size_t)2 * NC * CHK * CHK];// C B^T per (dir,chunk)
__device__ float g_Yd[(size_t)2 * L * DIN];      // Y (diag then += off + x*D)
__device__ float g_states[(size_t)2 * NC * NH * HD * NST];
__device__ float g_fd[L * NH];

// bf16 hi/lo split buffers for tensor-core GEMMs
__device__ __align__(16) __nv_bfloat16 g_uh[(size_t)L * DM];
__device__ __align__(16) __nv_bfloat16 g_ul[(size_t)L * DM];
__device__ __align__(16) __nv_bfloat16 g_wih[(size_t)DPROJ * DM];
__device__ __align__(16) __nv_bfloat16 g_wil[(size_t)DPROJ * DM];
__device__ __align__(16) __nv_bfloat16 g_ynh[(size_t)L * DIN];
__device__ __align__(16) __nv_bfloat16 g_ynl[(size_t)L * DIN];
__device__ __align__(16) __nv_bfloat16 g_woh[(size_t)DM * DIN];
__device__ __align__(16) __nv_bfloat16 g_wol[(size_t)DM * DIN];

__device__ __forceinline__ float sigmoidf_(float x) { return 1.f / (1.f + expf(-x)); }

__device__ __forceinline__ uint32_t smem_u32(const void* p) {
    uint32_t a;
    asm("{ .reg .u64 tmp; cvta.to.shared.u64 tmp, %1; cvt.u32.u64 %0, tmp; }" : "=r"(a) : "l"(p));
    return a;
}
__device__ __forceinline__ void cp_async16(uint32_t dst, const void* src, int srcsize) {
    asm volatile("cp.async.cg.shared.global [%0], [%1], 16, %2;"
                 :: "r"(dst), "l"(src), "r"(srcsize));
}
#define CP_COMMIT() asm volatile("cp.async.commit_group;" ::: "memory")
#define CP_WAIT1()  asm volatile("cp.async.wait_group 1;"  ::: "memory")
#define CP_WAIT0()  asm volatile("cp.async.wait_group 0;"  ::: "memory")

__device__ __forceinline__ void ldsm4(uint32_t* r, uint32_t addr) {
    asm volatile("ldmatrix.sync.aligned.m8n8.x4.shared.b16 {%0,%1,%2,%3}, [%4];"
                 : "=r"(r[0]), "=r"(r[1]), "=r"(r[2]), "=r"(r[3]) : "r"(addr));
}
__device__ __forceinline__ void mma16816(float* c, const uint32_t* a, uint32_t b0, uint32_t b1) {
    asm volatile("mma.sync.aligned.m16n8k16.row.col.f32.bf16.bf16.f32 "
                 "{%0,%1,%2,%3}, {%4,%5,%6,%7}, {%8,%9}, {%0,%1,%2,%3};"
                 : "+f"(c[0]), "+f"(c[1]), "+f"(c[2]), "+f"(c[3])
                 : "r"(a[0]), "r"(a[1]), "r"(a[2]), "r"(a[3]), "r"(b0), "r"(b1));
}

// ---------------- fp32 -> bf16 hi/lo split ----------------
__global__ void cvt_hilo_kernel(const float* __restrict__ x,
                                __nv_bfloat16* __restrict__ hi,
                                __nv_bfloat16* __restrict__ lo, size_t n) {
    size_t i = (size_t)blockIdx.x * blockDim.x + threadIdx.x;
    if (i >= n) return;
    float v = x[i];
    __nv_bfloat16 h = __float2bfloat16(v);
    hi[i] = h;
    lo[i] = __float2bfloat16(v - __bfloat162float(h));
}

// ============ mma.sync bf16 hi/lo-split GEMM: C[m,n] = sum_k A[m,k]*B[n,k] ============
// CTA 128x128 tile, 8 warps (2x4), warp 64x32. K-chunk 32, cp.async double buffer.
#define KC 32
#define APAD 40   // smem row stride in bf16 (80B, ldmatrix conflict-free)

__global__ __launch_bounds__(256, 2) void gemm_mma(
    const __nv_bfloat16* __restrict__ Ah, const __nv_bfloat16* __restrict__ Al,
    const __nv_bfloat16* __restrict__ Bh, const __nv_bfloat16* __restrict__ Bl,
    float* __restrict__ Cc, int Ntot, int Ktot) {
    extern __shared__ __align__(16) __nv_bfloat16 sm[];
    const int tid = threadIdx.x;
    const int bRow = blockIdx.y * 128, bCol = blockIdx.x * 128;
    const int wid = tid >> 5, lane = tid & 31;
    const int wm = (wid >> 2) * 64, wn = (wid & 3) * 32;

    // stage layout: [stage][op 0=Ah 1=Al 2=Bh 3=Bl][128][APAD]
    __nv_bfloat16* sp[2][4];
#pragma unroll
    for (int s = 0; s < 2; s++)
#pragma unroll
        for (int o = 0; o < 4; o++) sp[s][o] = sm + ((s * 4 + o) * 128 * APAD);

    float acc[4][4][4];
#pragma unroll
    for (int i = 0; i < 4; i++)
#pragma unroll
        for (int j = 0; j < 4; j++)
#pragma unroll
            for (int q = 0; q < 4; q++) acc[i][j][q] = 0.f;

    const int nst = Ktot / KC;

    // issue loads for stage s, chunk c
    auto issue = [&](int s, int c) {
        int kt = c * KC;
#pragma unroll
        for (int i = 0; i < 2; i++) {
            int u = tid + i * 256;          // 0..511 16B units
            int r = u >> 2, kc = (u & 3) * 8;
            size_t ga = (size_t)(bRow + r) * Ktot + kt + kc;
            cp_async16(smem_u32(sp[s][0] + r * APAD + kc), Ah + ga, 16);
            cp_async16(smem_u32(sp[s][1] + r * APAD + kc), Al + ga, 16);
            int ok = (bCol + r) < Ntot ? 16 : 0;
            size_t gb = ok ? ((size_t)(bCol + r) * Ktot + kt + kc) : 0;
            cp_async16(smem_u32(sp[s][2] + r * APAD + kc), Bh + gb, ok);
            cp_async16(smem_u32(sp[s][3] + r * APAD + kc), Bl + gb, ok);
        }
    };

    issue(0, 0);
    CP_COMMIT();

    const int ar = lane & 15, ac = (lane >> 4) * 8;
    for (int c = 0; c < nst; c++) {
        if (c + 1 < nst) { issue((c + 1) & 1, c + 1); CP_COMMIT(); CP_WAIT1(); }
        else CP_WAIT0();
        __syncthreads();
        const __nv_bfloat16* sa_h = sp[c & 1][0];
        const __nv_bfloat16* sa_l = sp[c & 1][1];
        const __nv_bfloat16* sb_h = sp[c & 1][2];
        const __nv_bfloat16* sb_l = sp[c & 1][3];
#pragma unroll
        for (int kk = 0; kk < 2; kk++) {
            int k0 = kk * 16;
            uint32_t bfh[2][4], bfl[2][4];
#pragma unroll
            for (int bt = 0; bt < 2; bt++) {
                ldsm4(bfh[bt], smem_u32(sb_h + (wn + bt * 16 + ar) * APAD + k0 + ac));
                ldsm4(bfl[bt], smem_u32(sb_l + (wn + bt * 16 + ar) * APAD + k0 + ac));
            }
#pragma unroll
            for (int mt = 0; mt < 4; mt++) {
                uint32_t afh[4], afl[4];
                ldsm4(afh, smem_u32(sa_h + (wm + mt * 16 + ar) * APAD + k0 + ac));
                ldsm4(afl, smem_u32(sa_l + (wm + mt * 16 + ar) * APAD + k0 + ac));
#pragma unroll
                for (int nt = 0; nt < 4; nt++) {
                    int bt = nt >> 1, sel = nt & 1;
                    mma16816(acc[mt][nt], afh, bfh[bt][sel], bfh[bt][sel + 2]);
                    mma16816(acc[mt][nt], afh, bfl[bt][sel], bfl[bt][sel + 2]);
                    mma16816(acc[mt][nt], afl, bfh[bt][sel], bfh[bt][sel + 2]);
                }
            }
        }
        __syncthreads();
    }

    // store: c0,c1 -> (row g, col 2t,2t+1); c2,c3 -> row g+8
    const int g = lane >> 2, t4 = lane & 3;
#pragma unroll
    for (int mt = 0; mt < 4; mt++) {
#pragma unroll
        for (int nt = 0; nt < 4; nt++) {
            int row = bRow + wm + mt * 16 + g;
            int col = bCol + wn + nt * 8 + t4 * 2;
            if (col < Ntot) {
                float* p0 = Cc + (size_t)row * Ntot + col;
                p0[0] = acc[mt][nt][0];
                p0[1] = acc[mt][nt][1];
                float* p1 = p0 + (size_t)8 * Ntot;
                p1[0] = acc[mt][nt][2];
                p1[1] = acc[mt][nt][3];
            }
        }
    }
}

// ---------------- generic NT SGEMM (small batched G = C B^T) --------
__global__ __launch_bounds__(256) void sgemm_nt(const float* __restrict__ A,
                                                const float* __restrict__ B,
                                                float* __restrict__ C,
                                                int M, int N, int K,
                                                long sA, long sB, long sC) {
    A += (size_t)blockIdx.z * sA;
    B += (size_t)blockIdx.z * sB;
    C += (size_t)blockIdx.z * sC;
    __shared__ float As[16][128];
    __shared__ float Bs[16][128];
    int tid = threadIdx.x;
    int bRow = blockIdx.y * 128, bCol = blockIdx.x * 128;
    int tx = tid & 15, ty = tid >> 4;
    float acc[8][8] = {};
    int lr = tid >> 2;
    int lk = (tid & 3) * 4;
    for (int kt = 0; kt < K; kt += 16) {
#pragma unroll
        for (int p = 0; p < 2; p++) {
            int r = lr + p * 64;
            int row = bRow + r;
            float4 v = make_float4(0.f, 0.f, 0.f, 0.f);
            if (row < M) v = *(const float4*)(A + (size_t)row * K + kt + lk);
            As[lk][r] = v.x; As[lk + 1][r] = v.y; As[lk + 2][r] = v.z; As[lk + 3][r] = v.w;
            int col = bCol + r;
            float4 w = make_float4(0.f, 0.f, 0.f, 0.f);
            if (col < N) w = *(const float4*)(B + (size_t)col * K + kt + lk);
            Bs[lk][r] = w.x; Bs[lk + 1][r] = w.y; Bs[lk + 2][r] = w.z; Bs[lk + 3][r] = w.w;
        }
        __syncthreads();
#pragma unroll
        for (int k = 0; k < 16; k++) {
            float ra[8], rb[8];
            *(float4*)ra       = *(const float4*)&As[k][ty * 8];
            *(float4*)(ra + 4) = *(const float4*)&As[k][ty * 8 + 4];
            *(float4*)rb       = *(const float4*)&Bs[k][tx * 8];
            *(float4*)(rb + 4) = *(const float4*)&Bs[k][tx * 8 + 4];
#pragma unroll
            for (int i = 0; i < 8; i++)
#pragma unroll
                for (int j = 0; j < 8; j++)
                    acc[i][j] += ra[i] * rb[j];
        }
        __syncthreads();
    }
    for (int i = 0; i < 8; i++) {
        int row = bRow + ty * 8 + i;
        if (row >= M) continue;
        for (int j = 0; j < 8; j++) {
            int col = bCol + tx * 8 + j;
            if (col < N) C[(size_t)row * N + col] = acc[i][j];
        }
    }
}

// ---------------- depthwise causal conv (k=4) + bias + silu ----------------
__global__ void conv_kernel(const float* __restrict__ cw, const float* __restrict__ cb) {
    size_t idx = (size_t)blockIdx.x * blockDim.x + threadIdx.x;
    if (idx >= (size_t)L * CONVD) return;
    int c = (int)(idx % CONVD);
    int t = (int)(idx / CONVD);
    float acc = cb[c];
#pragma unroll
    for (int k = 0; k < 4; k++) {
        int ts = t - 3 + k;
        if (ts >= 0) acc += cw[c * 4 + k] * g_zx[(size_t)ts * DPROJ + DIN + c];
    }
    g_xc[idx] = acc * sigmoidf_(acc);
}

// ---------------- dt (with direction flip) + softplus ----------------
__global__ void dt_kernel(const float* __restrict__ dt_bias) {
    int idx = blockIdx.x * blockDim.x + threadIdx.x;
    if (idx >= 2 * L * NH) return;
    int h = idx & 31;
    int t = (idx >> 5) & (L - 1);
    int dir = idx >> 17;
    int ts = dir ? (L - 1 - t) : t;
    float v = g_zx[(size_t)ts * DPROJ + DIN + CONVD + dir * NH + h] + dt_bias[h];
    g_dt2[idx] = (v > 20.f) ? v : log1pf(expf(v));
}

// ---------------- B/C split per direction (flip for dir1) ----------------
__global__ void prep_bc_kernel() {
    int idx = blockIdx.x * blockDim.x + threadIdx.x;
    if (idx >= 2 * L * NST) return;
    int n = idx & 127;
    int t = (idx >> 7) & (L - 1);
    int dir = idx >> 19;
    int ts = dir ? (L - 1 - t) : t;
    int off = dir ? 256 : 0;
    const float* p = g_xc + (size_t)ts * CONVD + DIN + off;
    g_Bm[idx] = p[n];
    g_Cm[idx] = p[NST + n];
}

// ---------------- x (flipped) * dt ----------------
__global__ void prep_x_kernel() {
    size_t idx = (size_t)blockIdx.x * blockDim.x + threadIdx.x;
    if (idx >= (size_t)2 * L * DIN) return;
    int d = (int)(idx & 2047);
    int t = (int)((idx >> 11) & (L - 1));
    int dir = (int)(idx >> 23);
    int ts = dir ? (L - 1 - t) : t;
    g_xdt[idx] = g_xc[(size_t)ts * CONVD + d] * g_dt2[((dir << 12) | t) * NH + (d >> 6)];
}

// ---------------- per-chunk cumsum of A*dt ----------------
__global__ void acs_kernel(const float* __restrict__ A_log) {
    int c = blockIdx.x, dir = blockIdx.y, h = threadIdx.x;
    float Ah = -expf(A_log[h]);
    float cum = 0.f;
    float* out = g_Acs + (((dir * NC + c) * NH + h) << 7);
    const float* dtp = g_dt2 + ((size_t)(dir * L + c * CHK)) * NH + h;
    for (int l = 0; l < CHK; l++) {
        cum += Ah * dtp[l * NH];
        out[l] = cum;
    }
}

// ---------------- per (dir,chunk,head): Y_diag = (G.*Lmat)@xdt ; states = B^T @ (decay.*xdt) ----
__global__ __launch_bounds__(256) void ydiag_states_kernel() {
    int b = blockIdx.x;
    int h = b & 31, c = (b >> 5) & 31, dir = b >> 10;
    int tid = threadIdx.x;
    __shared__ float sAcs[CHK];
    __shared__ float sMl[CHK][17];
    __shared__ float sXs[16][68];
    __shared__ float sB[16][132];
    __shared__ float sXd[16][68];
    if (tid < CHK) sAcs[tid] = g_Acs[(b << 7) + tid];
    __syncthreads();
    const float* Gp = g_G + ((size_t)(dir * NC + c) << 14);
    const float* Xp = g_xdt + ((size_t)(dir * L + c * CHK)) * DIN + h * HD;
    int tx = tid & 15, ty = tid >> 4;
    float acc[8][4] = {};
    int l0 = tid >> 1, skb = (tid & 1) * 8;
    for (int st = 0; st < 8; st++) {
#pragma unroll
        for (int i = 0; i < 8; i++) {
            int s = st * 16 + skb + i;
            float g = Gp[l0 * CHK + s];
            sMl[l0][skb + i] = (l0 >= s) ? g * expf(sAcs[l0] - sAcs[s]) : 0.f;
        }
        {
            int sk = tid >> 4, p0 = (tid & 15) * 4;
            float4 v = *(const float4*)(Xp + (size_t)(st * 16 + sk) * DIN + p0);
            sXs[sk][p0] = v.x; sXs[sk][p0 + 1] = v.y; sXs[sk][p0 + 2] = v.z; sXs[sk][p0 + 3] = v.w;
        }
        __syncthreads();
#pragma unroll
        for (int sk = 0; sk < 16; sk++) {
            float xb0 = sXs[sk][tx * 4], xb1 = sXs[sk][tx * 4 + 1];
            float xb2 = sXs[sk][tx * 4 + 2], xb3 = sXs[sk][tx * 4 + 3];
#pragma unroll
            for (int i = 0; i < 8; i++) {
                float m = sMl[ty * 8 + i][sk];
                acc[i][0] += m * xb0; acc[i][1] += m * xb1;
                acc[i][2] += m * xb2; acc[i][3] += m * xb3;
            }
        }
        __syncthreads();
    }
    float* Yp = g_Yd + ((size_t)(dir * L + c * CHK)) * DIN + h * HD;
#pragma unroll
    for (int i = 0; i < 8; i++)
#pragma unroll
        for (int j = 0; j < 4; j++)
            Yp[(size_t)(ty * 8 + i) * DIN + tx * 4 + j] = acc[i][j];

    // ---- states ----
    float accS[8][4] = {};
    int n0 = (tid & 31) * 4;
    int p0s = (tid >> 5) * 8;
    float lastA = sAcs[127];
    const float* Bp = g_Bm + ((size_t)(dir * L + c * CHK)) * NST;
    for (int lt = 0; lt < 8; lt++) {
        {
            int lk = tid >> 4, nb = (tid & 15) * 8;
            float4 v0 = *(const float4*)(Bp + (size_t)(lt * 16 + lk) * NST + nb);
            float4 v1 = *(const float4*)(Bp + (size_t)(lt * 16 + lk) * NST + nb + 4);
            sB[lk][nb] = v0.x; sB[lk][nb + 1] = v0.y; sB[lk][nb + 2] = v0.z; sB[lk][nb + 3] = v0.w;
            sB[lk][nb + 4] = v1.x; sB[lk][nb + 5] = v1.y; sB[lk][nb + 6] = v1.z; sB[lk][nb + 7] = v1.w;
            int pb = (tid & 15) * 4;
            float dec = expf(lastA - sAcs[lt * 16 + lk]);
            float4 xv = *(const float4*)(Xp + (size_t)(lt * 16 + lk) * DIN + pb);
            sXd[lk][pb] = xv.x * dec; sXd[lk][pb + 1] = xv.y * dec;
            sXd[lk][pb + 2] = xv.z * dec; sXd[lk][pb + 3] = xv.w * dec;
        }
        __syncthreads();
#pragma unroll
        for (int lk2 = 0; lk2 < 16; lk2++) {
            float pv[8];
#pragma unroll
            for (int i = 0; i < 8; i++) pv[i] = sXd[lk2][p0s + i];
            float nv0 = sB[lk2][n0], nv1 = sB[lk2][n0 + 1];
            float nv2 = sB[lk2][n0 + 2], nv3 = sB[lk2][n0 + 3];
#pragma unroll
            for (int i = 0; i < 8; i++) {
                accS[i][0] += pv[i] * nv0; accS[i][1] += pv[i] * nv1;
                accS[i][2] += pv[i] * nv2; accS[i][3] += pv[i] * nv3;
            }
        }
        __syncthreads();
    }
    float* Sp = g_states + ((size_t)b << 13);
#pragma unroll
    for (int i = 0; i < 8; i++)
#pragma unroll
        for (int j = 0; j < 4; j++)
            Sp[(size_t)(p0s + i) * NST + n0 + j] = accS[i][j];
}

// ---------------- inter-chunk recurrence ----------------
__global__ void recur_kernel() {
    int b = blockIdx.x;
    int dir = b >> 5, h = b & 31;
    int tid = threadIdx.x;
    float Hreg[32];
#pragma unroll
    for (int k = 0; k < 32; k++) Hreg[k] = 0.f;
    for (int c = 0; c < NC; c++) {
        int sb = (dir * NC + c) * NH + h;
        float dec = expf(g_Acs[(sb << 7) + 127]);
        size_t base = ((size_t)sb << 13);
#pragma unroll
        for (int k = 0; k < 32; k++) {
            size_t off = base + tid + k * 256;
            float s = g_states[off];
            g_states[off] = Hreg[k];
            Hreg[k] = dec * Hreg[k] + s;
        }
    }
}

// ---------------- Y_off = exp(Acs[l]) * C @ state^T ; Yd += Y_off + x*D ----------------
__global__ __launch_bounds__(256) void yoff_kernel(const float* __restrict__ Dv) {
    int b = blockIdx.x;
    int h = b & 31, c = (b >> 5) & 31, dir = b >> 10;
    int tid = threadIdx.x;
    __shared__ float sAcs[CHK];
    __shared__ float sC[CHK][17];
    __shared__ float sS[64][17];
    if (tid < CHK) sAcs[tid] = g_Acs[(b << 7) + tid];
    __syncthreads();
    const float* Cp = g_Cm + ((size_t)(dir * L + c * CHK)) * NST;
    const float* Sp = g_states + ((size_t)b << 13);
    int tx = tid & 15, ty = tid >> 4;
    float acc[8][4] = {};
    int l0 = tid >> 1, nkb = (tid & 1) * 8;
    int p1 = tid >> 2, nkb2 = (tid & 3) * 4;
    for (int nt = 0; nt < 8; nt++) {
#pragma unroll
        for (int i = 0; i < 8; i++)
            sC[l0][nkb + i] = Cp[(size_t)l0 * NST + nt * 16 + nkb + i];
        {
            float4 v = *(const float4*)(Sp + (size_t)p1 * NST + nt * 16 + nkb2);
            sS[p1][nkb2] = v.x; sS[p1][nkb2 + 1] = v.y;
            sS[p1][nkb2 + 2] = v.z; sS[p1][nkb2 + 3] = v.w;
        }
        __syncthreads();
#pragma unroll
        for (int nk = 0; nk < 16; nk++) {
            float sv0 = sS[tx * 4][nk], sv1 = sS[tx * 4 + 1][nk];
            float sv2 = sS[tx * 4 + 2][nk], sv3 = sS[tx * 4 + 3][nk];
#pragma unroll
            for (int i = 0; i < 8; i++) {
                float cv = sC[ty * 8 + i][nk];
                acc[i][0] += cv * sv0; acc[i][1] += cv * sv1;
                acc[i][2] += cv * sv2; acc[i][3] += cv * sv3;
            }
        }
        __syncthreads();
    }
    float Dh = Dv[h];
    float* Yp = g_Yd + ((size_t)(dir * L + c * CHK)) * DIN + h * HD;
#pragma unroll
    for (int i = 0; i < 8; i++) {
        int l = ty * 8 + i;
        float e = expf(sAcs[l]);
        int tglob = c * CHK + l;
        int ts = dir ? (L - 1 - tglob) : tglob;
        const float* xrow = g_xc + (size_t)ts * CONVD + h * HD;
#pragma unroll
        for (int j = 0; j < 4; j++) {
            int p = tx * 4 + j;
            size_t o = (size_t)l * DIN + p;
            Yp[o] = Yp[o] + e * acc[i][j] + xrow[p] * Dh;
        }
    }
}

// ---------------- fd[t,h] = x_og[t] . fc_D_w[h] + D[h] ----------------
__global__ void fcD_kernel(const float* __restrict__ W, const float* __restrict__ Dv) {
    int t = blockIdx.x;
    __shared__ float sx[DIN];
    int tid = threadIdx.x;
#pragma unroll
    for (int k = 0; k < 8; k++) sx[tid + k * 256] = g_xc[(size_t)t * CONVD + tid + k * 256];
    __syncthreads();
    int warp = tid >> 5, lane = tid & 31;
    for (int q = 0; q < 4; q++) {
        int h = warp * 4 + q;
        const float* wr = W + (size_t)h * DIN;
        float acc = 0.f;
        for (int i = 0; i < 64; i++) {
            int d = i * 32 + lane;
            acc += sx[d] * wr[d];
        }
        for (int o = 16; o > 0; o >>= 1) acc += __shfl_down_sync(0xffffffffu, acc, o);
        if (lane == 0) g_fd[t * NH + h] = acc + Dv[h];
    }
}

// ---------------- shift + merge dirs + skip + gate + RMSNorm -> bf16 hi/lo ----------------
__global__ void combine_kernel(const float* __restrict__ norm_w) {
    int t = blockIdx.x;
    int tid = threadIdx.x;
    __shared__ float red[256];
    __shared__ float sc;
    float yg[8];
    float ss = 0.f;
#pragma unroll
    for (int k = 0; k < 8; k++) {
        int d = tid + k * 256;
        float yfw = (t > 0) ? g_Yd[((size_t)(t - 1)) * DIN + d] : 0.f;
        float ybw = (t < L - 1) ? g_Yd[((size_t)(L + (L - 2 - t))) * DIN + d] : 0.f;
        float x = g_xc[(size_t)t * CONVD + d];
        float fdv = g_fd[t * NH + (d >> 6)];
        float z = g_zx[(size_t)t * DPROJ + d];
        float v = (yfw + ybw + x * fdv) * (z * sigmoidf_(z));
        yg[k] = v;
        ss += v * v;
    }
    red[tid] = ss;
    __syncthreads();
    for (int o = 128; o > 0; o >>= 1) {
        if (tid < o) red[tid] += red[tid + o];
        __syncthreads();
    }
    if (tid == 0) sc = rsqrtf(red[0] * (1.f / DIN) + EPSV);
    __syncthreads();
    float s = sc;
#pragma unroll
    for (int k = 0; k < 8; k++) {
        int d = tid + k * 256;
        float v = yg[k] * s * norm_w[d];
        __nv_bfloat16 hv = __float2bfloat16(v);
        g_ynh[(size_t)t * DIN + d] = hv;
        g_ynl[(size_t)t * DIN + d] = __float2bfloat16(v - __bfloat162float(hv));
    }
}

extern "C" void kernel_launch(void* const* d_in, const int* in_sizes, int n_in,
                              void* d_out, int out_size) {
    const float* u          = (const float*)d_in[0];
    const float* in_proj_w  = (const float*)d_in[1];
    const float* conv_w     = (const float*)d_in[2];
    const float* conv_b     = (const float*)d_in[3];
    const float* dt_bias    = (const float*)d_in[4];
    const float* A_log      = (const float*)d_in[5];
    const float* Dv         = (const float*)d_in[6];
    const float* fc_D_w     = (const float*)d_in[7];
    const float* norm_w     = (const float*)d_in[8];
    const float* out_proj_w = (const float*)d_in[9];
    float* out = (float*)d_out;

    float *zx, *Bm, *Cm, *G;
    __nv_bfloat16 *uh, *ul, *wih, *wil, *ynh, *ynl, *woh, *wol;
    cudaGetSymbolAddress((void**)&zx, g_zx);
    cudaGetSymbolAddress((void**)&Bm, g_Bm);
    cudaGetSymbolAddress((void**)&Cm, g_Cm);
    cudaGetSymbolAddress((void**)&G, g_G);
    cudaGetSymbolAddress((void**)&uh, g_uh);
    cudaGetSymbolAddress((void**)&ul, g_ul);
    cudaGetSymbolAddress((void**)&wih, g_wih);
    cudaGetSymbolAddress((void**)&wil, g_wil);
    cudaGetSymbolAddress((void**)&ynh, g_ynh);
    cudaGetSymbolAddress((void**)&ynl, g_ynl);
    cudaGetSymbolAddress((void**)&woh, g_woh);
    cudaGetSymbolAddress((void**)&wol, g_wol);

    const int smemB = 2 * 4 * 128 * APAD * 2;  // 81920 B
    cudaFuncSetAttribute(gemm_mma, cudaFuncAttributeMaxDynamicSharedMemorySize, smemB);

    // 0) split inputs/weights into bf16 hi/lo
    cvt_hilo_kernel<<<((size_t)L * DM + 255) / 256, 256>>>(u, uh, ul, (size_t)L * DM);
    cvt_hilo_kernel<<<((size_t)DPROJ * DM + 255) / 256, 256>>>(in_proj_w, wih, wil, (size_t)DPROJ * DM);
    cvt_hilo_kernel<<<((size_t)DM * DIN + 255) / 256, 256>>>(out_proj_w, woh, wol, (size_t)DM * DIN);

    // 1) in_proj: (4096 x 1024) @ (4672 x 1024)^T  -- mma.sync bf16 hi/lo split
    gemm_mma<<<dim3((DPROJ + 127) / 128, L / 128), 256, smemB>>>(uh, ul, wih, wil, zx, DPROJ, DM);
    // 2) conv + silu
    conv_kernel<<<((size_t)L * CONVD + 255) / 256, 256>>>(conv_w, conv_b);
    // 3) dt softplus (both dirs)
    dt_kernel<<<(2 * L * NH + 255) / 256, 256>>>(dt_bias);
    // 4) B/C and x*dt prep
    prep_bc_kernel<<<(2 * L * NST + 255) / 256, 256>>>();
    prep_x_kernel<<<((size_t)2 * L * DIN + 255) / 256, 256>>>();
    // 5) per-chunk cumsum of A*dt
    acs_kernel<<<dim3(NC, 2), 32>>>(A_log);
    // 6) G = C B^T per (dir,chunk), batched
    sgemm_nt<<<dim3(1, 1, 2 * NC), 256>>>(Cm, Bm, G, CHK, CHK, NST,
                                          CHK * NST, CHK * NST, CHK * CHK);
    // 7) Y_diag + chunk states
    ydiag_states_kernel<<<2 * NC * NH, 256>>>();
    // 8) inter-chunk recurrence
    recur_kernel<<<2 * NH, 256>>>();
    // 9) Y_off + x*D
    yoff_kernel<<<2 * NC * NH, 256>>>(Dv);
    // 10) fd
    fcD_kernel<<<L, 256>>>(fc_D_w, Dv);
    // 11) shift/merge/gate/RMSNorm (writes bf16 hi/lo)
    combine_kernel<<<L, 256>>>(norm_w);
    // 12) out_proj: (4096 x 2048) @ (1024 x 2048)^T -- mma.sync bf16 hi/lo split
    gemm_mma<<<dim3(DM / 128, L / 128), 256, smemB>>>(ynh, ynl, woh, wol, out, DM, DIN);
}